// round 15
// baseline (speedup 1.0000x reference)
#include <cuda_runtime.h>
#include <cuda_bf16.h>
#include <cuda_fp16.h>
#include <cstdint>

#define SQ 4096
#define DM 1024
#define NH 16
#define HS 64
#define QSCALE 0.125f
#define LOG2E 1.4426950408889634f
#define NEG -1e9f

// -------- scratch (no allocations allowed) --------
__device__ __align__(16) __half g_x16[SQ * DM];        // activations fp16 (x, then attn-out)
__device__ __align__(16) __half g_w16[4 * DM * DM];    // weights fp16
__device__ __align__(16) __half g_q16[NH * SQ * HS];   // q fp16 (exp2-domain scaled)
__device__ __align__(16) __half g_k16[NH * SQ * HS];   // k fp16
__device__ __align__(16) __half g_v16[NH * SQ * HS];   // v fp16

// ============================================================================
// helpers
// ============================================================================
__device__ __forceinline__ uint32_t smem_u32(const void* p) {
    uint32_t a;
    asm("{ .reg .u64 t; cvta.to.shared.u64 t, %1; cvt.u32.u64 %0, t; }" : "=r"(a) : "l"(p));
    return a;
}

#define LDSM_X4(r0, r1, r2, r3, addr) \
    asm volatile("ldmatrix.sync.aligned.m8n8.x4.shared.b16 {%0,%1,%2,%3}, [%4];" \
                 : "=r"(r0), "=r"(r1), "=r"(r2), "=r"(r3) : "r"(addr))

#define LDSM_X4_T(r0, r1, r2, r3, addr) \
    asm volatile("ldmatrix.sync.aligned.m8n8.x4.trans.shared.b16 {%0,%1,%2,%3}, [%4];" \
                 : "=r"(r0), "=r"(r1), "=r"(r2), "=r"(r3) : "r"(addr))

__device__ __forceinline__ void mma_f16(float4& d, const uint32_t* a, uint32_t b0, uint32_t b1) {
    asm volatile("mma.sync.aligned.m16n8k16.row.col.f32.f16.f16.f32 "
                 "{%0,%1,%2,%3}, {%4,%5,%6,%7}, {%8,%9}, {%0,%1,%2,%3};"
                 : "+f"(d.x), "+f"(d.y), "+f"(d.z), "+f"(d.w)
                 : "r"(a[0]), "r"(a[1]), "r"(a[2]), "r"(a[3]), "r"(b0), "r"(b1));
}

__device__ __forceinline__ void cp16(uint32_t s, const void* g) {
    asm volatile("cp.async.cg.shared.global [%0], [%1], 16;" :: "r"(s), "l"(g));
}
__device__ __forceinline__ void cp_commit() {
    asm volatile("cp.async.commit_group;" ::: "memory");
}
template <int N>
__device__ __forceinline__ void cp_wait() {
    asm volatile("cp.async.wait_group %0;" :: "n"(N) : "memory");
}

__device__ __forceinline__ unsigned pack_h2(float a, float b) {
    __half2 h = __floats2half2_rn(a, b);
    return *(unsigned*)&h;
}

// ============================================================================
// fused split: z<4 -> weights fp16, z==4 -> x fp16
// ============================================================================
__global__ __launch_bounds__(256)
void split5_kernel(const float4* __restrict__ w0, const float4* __restrict__ w1,
                   const float4* __restrict__ w2, const float4* __restrict__ w3,
                   const float4* __restrict__ x)
{
    const int z = blockIdx.z;
    const float4* src;
    uint2* dst;
    int n4;
    if (z < 4) {
        src = (z == 0) ? w0 : (z == 1) ? w1 : (z == 2) ? w2 : w3;
        dst = (uint2*)(g_w16 + (size_t)z * DM * DM);
        n4 = DM * DM / 4;
    } else {
        src = x;
        dst = (uint2*)g_x16;
        n4 = SQ * DM / 4;
    }
    for (int i = blockIdx.x * blockDim.x + threadIdx.x; i < n4;
         i += gridDim.x * blockDim.x) {
        float4 v = src[i];
        dst[i] = make_uint2(pack_h2(v.x, v.y), pack_h2(v.z, v.w));
    }
}

// ============================================================================
// GEMM via mma.sync: out = A @ W^T + bias.  A fp16, W fp16.
// 128x128 tile, K-chunk 32, RING-4 cp.async (wait<2>), XOR swizzle,
// ONE sync per chunk. Refill issued BEFORE compute; ALL chunk fragments
// loaded up-front (12 LDSM back-to-back), then 32 straight-line MMAs.
// ============================================================================
#define G_STG 16384
#define GA 0
#define GB 8192

__device__ __forceinline__ uint32_t gswz(int row, int ch) {
    return (uint32_t)(row * 64 + ((ch ^ ((row >> 1) & 3)) << 4));
}

template <int MODE>
__global__ __launch_bounds__(256, 2)
void gemm_mma(const __half* __restrict__ A,
              int wslot,
              const float* __restrict__ b0p, const float* __restrict__ b1p,
              const float* __restrict__ b2p,
              float* __restrict__ out)
{
    extern __shared__ __align__(16) char smem[];
    const uint32_t sb = smem_u32(smem);

    const int t = threadIdx.x;
    const int warp = t >> 5, lane = t & 31;
    const int warpM = warp >> 2, warpN = warp & 3;
    const int z = blockIdx.z;
    const int blockM = blockIdx.y * 128;
    const int blockN = blockIdx.x * 128;

    const __half* W = g_w16 + (size_t)(wslot + z) * DM * DM;
    const float* bias = (z == 0) ? b0p : ((z == 1) ? b1p : b2p);

    // loader: thread t -> row (t&127) of array (t>>7): 0 = A, 1 = W; 4 cp16/row
    const int lrow = t & 127;
    const int larr = t >> 7;
    const __half* lsrc = larr ? (W + (size_t)(blockN + lrow) * DM)
                              : (A + (size_t)(blockM + lrow) * DM);
    const uint32_t lbase = (uint32_t)(larr ? GB : GA);

    float4 acc[4][4];
#pragma unroll
    for (int i = 0; i < 4; i++)
#pragma unroll
        for (int j = 0; j < 4; j++) acc[i][j] = make_float4(0.f, 0.f, 0.f, 0.f);

    // prologue: chunks 0,1,2 -> stages 0,1,2 (3 commit groups)
#pragma unroll
    for (int pc = 0; pc < 3; pc++) {
        const uint32_t stg = sb + pc * G_STG + lbase;
        const int kc = pc * 32;
#pragma unroll
        for (int ch = 0; ch < 4; ch++)
            cp16(stg + gswz(lrow, ch), lsrc + kc + ch * 8);
        cp_commit();
    }

    for (int c = 0; c < 32; c++) {
        cp_wait<2>();
        __syncthreads();

        // refill FIRST (stage (c+3)&3 last read at iter c-1; top sync fences)
        if (c + 3 < 32) {
            const uint32_t stg2 = sb + ((c + 3) & 3) * G_STG + lbase;
            const int kc = (c + 3) * 32;
#pragma unroll
            for (int ch = 0; ch < 4; ch++)
                cp16(stg2 + gswz(lrow, ch), lsrc + kc + ch * 8);
        }
        cp_commit();

        const uint32_t stg = sb + (c & 3) * G_STG;

        // load ALL fragments for this chunk (latencies overlap), then MMAs
        uint32_t aF[2][4][4], bF[2][4][2];
#pragma unroll
        for (int ks = 0; ks < 2; ks++) {
            const int chA = 2 * ks + (lane >> 4);
#pragma unroll
            for (int i = 0; i < 4; i++) {
                const int arow = warpM * 64 + i * 16 + (lane & 15);
                LDSM_X4(aF[ks][i][0], aF[ks][i][1], aF[ks][i][2], aF[ks][i][3],
                        stg + GA + gswz(arow, chA));
            }
        }
#pragma unroll
        for (int ks = 0; ks < 2; ks++) {
            const int chB = 2 * ks + ((lane >> 3) & 1);
#pragma unroll
            for (int p = 0; p < 2; p++) {
                const int brow = warpN * 32 + p * 16 + ((lane >> 4) * 8) + (lane & 7);
                uint32_t m0, m1, m2, m3;
                LDSM_X4(m0, m1, m2, m3, stg + GB + gswz(brow, chB));
                bF[ks][2 * p][0] = m0; bF[ks][2 * p][1] = m1;
                bF[ks][2 * p + 1][0] = m2; bF[ks][2 * p + 1][1] = m3;
            }
        }
#pragma unroll
        for (int ks = 0; ks < 2; ks++)
#pragma unroll
            for (int i = 0; i < 4; i++)
#pragma unroll
                for (int j = 0; j < 4; j++)
                    mma_f16(acc[i][j], aF[ks][i], bF[ks][j][0], bF[ks][j][1]);
    }

    // epilogue
    const float sc = (MODE == 0 && z == 0) ? (QSCALE * LOG2E) : 1.f;
#pragma unroll
    for (int i = 0; i < 4; i++) {
#pragma unroll
        for (int j = 0; j < 4; j++) {
            const int row0 = blockM + warpM * 64 + i * 16 + (lane >> 2);
            const int row1 = row0 + 8;
            const int col = blockN + warpN * 32 + j * 8 + (lane & 3) * 2;
            const float bx = bias[col], by = bias[col + 1];
            const float vx = (acc[i][j].x + bx) * sc;
            const float vy = (acc[i][j].y + by) * sc;
            const float vz = (acc[i][j].z + bx) * sc;
            const float vw = (acc[i][j].w + by) * sc;
            if (MODE == 1) {
                *(float2*)(out + (size_t)row0 * DM + col) = make_float2(vx, vy);
                *(float2*)(out + (size_t)row1 * DM + col) = make_float2(vz, vw);
            } else {
                const int hh = col >> 6, d = col & 63;
                const size_t a0 = (size_t)hh * SQ * HS + (size_t)row0 * HS + d;
                const size_t a1 = (size_t)hh * SQ * HS + (size_t)row1 * HS + d;
                __half* dst = (z == 0) ? g_q16 : ((z == 1) ? g_k16 : g_v16);
                *(uint32_t*)(dst + a0) = pack_h2(vx, vy);
                *(uint32_t*)(dst + a1) = pack_h2(vz, vw);
            }
        }
    }
}

// ============================================================================
// Flash attention: RING-4 cp.async (wait<2>), refill before compute,
// ONE sync per k-tile, exp2f softmax. Output fp16 -> g_x16.
// ============================================================================
#define GSTB 144
#define KVBUF 18432
#define OFF_K 0
#define OFF_V 9216
#define ATTN_SMEM_TOT (4 * KVBUF)   // 73728

__global__ __launch_bounds__(256, 2)
void attn_mma()
{
    extern __shared__ __align__(16) char smem[];
    const uint32_t sb = smem_u32(smem);

    const int h  = blockIdx.y;
    const int qb = gridDim.x - 1 - blockIdx.x;
    const int t = threadIdx.x;
    const int warp = t >> 5, lane = t & 31;

    const size_t hbase = (size_t)h * SQ * HS;

    // ---- stage Q tile (128 rows, fp16) — region reused by ring after ----
#pragma unroll
    for (int it = 0; it < 2; it++) {
        const int idx = it * 256 + t;
        const int r = idx >> 2;
        const int c8 = (idx & 3) * 16;
        const size_t g = hbase + (size_t)(qb * 128 + r) * HS + c8;
        const uint32_t so = r * GSTB + c8 * 2;
        *(uint4*)(smem + so) = *(const uint4*)(g_q16 + g);
        *(uint4*)(smem + so + 16) = *(const uint4*)(g_q16 + g + 8);
    }
    __syncthreads();

    uint32_t qh[4][4];
#pragma unroll
    for (int ks = 0; ks < 4; ks++) {
        const uint32_t ro = (warp * 16 + (lane & 15)) * GSTB + (ks * 16 + (lane >> 4) * 8) * 2;
        LDSM_X4(qh[ks][0], qh[ks][1], qh[ks][2], qh[ks][3], sb + ro);
    }
    __syncthreads();   // Q consumed before ring reuse

    const int nkt = 2 * qb + 2;

    // prologue: tiles 0..2 -> buffers 0..2 (guarded; 3 commits)
#pragma unroll
    for (int i = 0; i < 3; i++) {
        if (i < nkt) {
            const uint32_t bufb = sb + i * KVBUF;
            const int r = t >> 2;
            const int c8 = (t & 3) * 16;
            const size_t g = hbase + (size_t)(i * 64 + r) * HS + c8;
            const uint32_t so = r * GSTB + c8 * 2;
            cp16(bufb + OFF_K + so,      g_k16 + g);
            cp16(bufb + OFF_K + so + 16, g_k16 + g + 8);
            cp16(bufb + OFF_V + so,      g_v16 + g);
            cp16(bufb + OFF_V + so + 16, g_v16 + g + 8);
        }
        cp_commit();
    }

    float4 o[8];
#pragma unroll
    for (int f = 0; f < 8; f++) o[f] = make_float4(0.f, 0.f, 0.f, 0.f);
    float m0 = -1e30f, m1 = -1e30f, l0s = 0.f, l1s = 0.f;

    for (int kt = 0; kt < nkt; kt++) {
        cp_wait<2>();
        __syncthreads();

        // refill FIRST (buffer (kt+3)&3 last read at kt-1; top sync fences)
        if (kt + 3 < nkt) {
            const uint32_t bufb = sb + ((kt + 3) & 3) * KVBUF;
            const int r = t >> 2;
            const int c8 = (t & 3) * 16;
            const size_t g = hbase + (size_t)((kt + 3) * 64 + r) * HS + c8;
            const uint32_t so = r * GSTB + c8 * 2;
            cp16(bufb + OFF_K + so,      g_k16 + g);
            cp16(bufb + OFF_K + so + 16, g_k16 + g + 8);
            cp16(bufb + OFF_V + so,      g_v16 + g);
            cp16(bufb + OFF_V + so + 16, g_v16 + g + 8);
        }
        cp_commit();

        const uint32_t kvb = sb + (kt & 3) * KVBUF;

        float4 s[8];
#pragma unroll
        for (int f = 0; f < 8; f++) s[f] = make_float4(0.f, 0.f, 0.f, 0.f);

#pragma unroll
        for (int ks = 0; ks < 4; ks++) {
            const uint32_t bcol = (ks * 16 + ((lane >> 3) & 1) * 8) * 2;
#pragma unroll
            for (int p = 0; p < 4; p++) {
                const uint32_t brow = (p * 16 + ((lane >> 4) * 8) + (lane & 7)) * GSTB;
                uint32_t k0, k1, k2, k3;
                LDSM_X4(k0, k1, k2, k3, kvb + OFF_K + brow + bcol);
                mma_f16(s[2 * p],     qh[ks], k0, k1);
                mma_f16(s[2 * p + 1], qh[ks], k2, k3);
            }
        }

        if (kt * 64 + 63 > qb * 128 + warp * 16) {
            const int q0 = qb * 128 + warp * 16 + (lane >> 2);
            const int q1 = q0 + 8;
#pragma unroll
            for (int f = 0; f < 8; f++) {
                const int kc = kt * 64 + f * 8 + (lane & 3) * 2;
                if (kc > q0)     s[f].x = NEG;
                if (kc + 1 > q0) s[f].y = NEG;
                if (kc > q1)     s[f].z = NEG;
                if (kc + 1 > q1) s[f].w = NEG;
            }
        }

        float rmax0 = NEG, rmax1 = NEG;
#pragma unroll
        for (int f = 0; f < 8; f++) {
            rmax0 = fmaxf(rmax0, fmaxf(s[f].x, s[f].y));
            rmax1 = fmaxf(rmax1, fmaxf(s[f].z, s[f].w));
        }
        rmax0 = fmaxf(rmax0, __shfl_xor_sync(0xffffffffu, rmax0, 1));
        rmax0 = fmaxf(rmax0, __shfl_xor_sync(0xffffffffu, rmax0, 2));
        rmax1 = fmaxf(rmax1, __shfl_xor_sync(0xffffffffu, rmax1, 1));
        rmax1 = fmaxf(rmax1, __shfl_xor_sync(0xffffffffu, rmax1, 2));

        const float mn0 = fmaxf(m0, rmax0);
        const float mn1 = fmaxf(m1, rmax1);
        const float c0 = exp2f(m0 - mn0);
        const float c1 = exp2f(m1 - mn1);

        float rs0 = 0.f, rs1 = 0.f;
#pragma unroll
        for (int f = 0; f < 8; f++) {
            s[f].x = exp2f(s[f].x - mn0);
            s[f].y = exp2f(s[f].y - mn0);
            s[f].z = exp2f(s[f].z - mn1);
            s[f].w = exp2f(s[f].w - mn1);
            rs0 += s[f].x + s[f].y;
            rs1 += s[f].z + s[f].w;
        }
        rs0 += __shfl_xor_sync(0xffffffffu, rs0, 1);
        rs0 += __shfl_xor_sync(0xffffffffu, rs0, 2);
        rs1 += __shfl_xor_sync(0xffffffffu, rs1, 1);
        rs1 += __shfl_xor_sync(0xffffffffu, rs1, 2);

        l0s = l0s * c0 + rs0;
        l1s = l1s * c1 + rs1;
        m0 = mn0; m1 = mn1;
#pragma unroll
        for (int f = 0; f < 8; f++) {
            o[f].x *= c0; o[f].y *= c0; o[f].z *= c1; o[f].w *= c1;
        }

#pragma unroll
        for (int ks = 0; ks < 4; ks++) {
            uint32_t ap[4];
            ap[0] = pack_h2(s[2 * ks].x,     s[2 * ks].y);
            ap[1] = pack_h2(s[2 * ks].z,     s[2 * ks].w);
            ap[2] = pack_h2(s[2 * ks + 1].x, s[2 * ks + 1].y);
            ap[3] = pack_h2(s[2 * ks + 1].z, s[2 * ks + 1].w);

            const uint32_t vrow = (ks * 16 + (lane & 7) + ((lane >> 3) & 1) * 8) * GSTB;
#pragma unroll
            for (int g = 0; g < 4; g++) {
                const uint32_t vcol = (g * 16 + (lane >> 4) * 8) * 2;
                uint32_t v0, v1, v2, v3;
                LDSM_X4_T(v0, v1, v2, v3, kvb + OFF_V + vrow + vcol);
                mma_f16(o[2 * g],     ap, v0, v1);
                mma_f16(o[2 * g + 1], ap, v2, v3);
            }
        }
    }

    // ---- normalize + write fp16 (feeds O projection) ----
    const float inv0 = 1.f / l0s;
    const float inv1 = 1.f / l1s;
    const int r0 = qb * 128 + warp * 16 + (lane >> 2);
    const int r1 = r0 + 8;
#pragma unroll
    for (int f = 0; f < 8; f++) {
        const int col = h * HS + f * 8 + (lane & 3) * 2;
        *(uint32_t*)(g_x16 + (size_t)r0 * DM + col) = pack_h2(o[f].x * inv0, o[f].y * inv0);
        *(uint32_t*)(g_x16 + (size_t)r1 * DM + col) = pack_h2(o[f].z * inv1, o[f].w * inv1);
    }
}

// ============================================================================
// launch
// ============================================================================
extern "C" void kernel_launch(void* const* d_in, const int* in_sizes, int n_in,
                              void* d_out, int out_size)
{
    (void)in_sizes; (void)n_in; (void)out_size;
    const float* x  = (const float*)d_in[0];
    const float* wq = (const float*)d_in[1];
    const float* bq = (const float*)d_in[2];
    const float* wk = (const float*)d_in[3];
    const float* bk = (const float*)d_in[4];
    const float* wv = (const float*)d_in[5];
    const float* bv = (const float*)d_in[6];
    const float* wo = (const float*)d_in[7];
    const float* bo = (const float*)d_in[8];
    float* out = (float*)d_out;

    __half* x16;
    cudaGetSymbolAddress((void**)&x16, g_x16);

    const int GEMM_SMEM = 4 * G_STG;   // 65536
    cudaFuncSetAttribute(gemm_mma<0>,
                         cudaFuncAttributeMaxDynamicSharedMemorySize, GEMM_SMEM);
    cudaFuncSetAttribute(gemm_mma<1>,
                         cudaFuncAttributeMaxDynamicSharedMemorySize, GEMM_SMEM);
    cudaFuncSetAttribute(attn_mma,
                         cudaFuncAttributeMaxDynamicSharedMemorySize, ATTN_SMEM_TOT);

    split5_kernel<<<dim3(512, 1, 5), 256>>>((const float4*)wq, (const float4*)wk,
                                            (const float4*)wv, (const float4*)wo,
                                            (const float4*)x);

    gemm_mma<0><<<dim3(DM / 128, SQ / 128, 3), 256, GEMM_SMEM>>>(
        x16, 0, bq, bk, bv, nullptr);

    attn_mma<<<dim3(SQ / 128, NH), 256, ATTN_SMEM_TOT>>>();

    gemm_mma<1><<<dim3(DM / 128, SQ / 128, 1), 256, GEMM_SMEM>>>(
        x16, 3, bo, bo, bo, out);
}

// round 17
// speedup vs baseline: 1.0499x; 1.0499x over previous
#include <cuda_runtime.h>
#include <cuda_bf16.h>
#include <cuda_fp16.h>
#include <cstdint>

#define SQ 4096
#define DM 1024
#define NH 16
#define HS 64
#define QSCALE 0.125f
#define LOG2E 1.4426950408889634f
#define NEG -1e9f

// -------- scratch (no allocations allowed) --------
__device__ __align__(16) __half g_x16[SQ * DM];
__device__ __align__(16) __half g_w16[4 * DM * DM];
__device__ __align__(16) __half g_q16[NH * SQ * HS];
__device__ __align__(16) __half g_k16[NH * SQ * HS];
__device__ __align__(16) __half g_v16[NH * SQ * HS];

// ============================================================================
// helpers
// ============================================================================
__device__ __forceinline__ uint32_t smem_u32(const void* p) {
    uint32_t a;
    asm("{ .reg .u64 t; cvta.to.shared.u64 t, %1; cvt.u32.u64 %0, t; }" : "=r"(a) : "l"(p));
    return a;
}

#define LDSM_X4(r0, r1, r2, r3, addr) \
    asm volatile("ldmatrix.sync.aligned.m8n8.x4.shared.b16 {%0,%1,%2,%3}, [%4];" \
                 : "=r"(r0), "=r"(r1), "=r"(r2), "=r"(r3) : "r"(addr))

#define LDSM_X4_T(r0, r1, r2, r3, addr) \
    asm volatile("ldmatrix.sync.aligned.m8n8.x4.trans.shared.b16 {%0,%1,%2,%3}, [%4];" \
                 : "=r"(r0), "=r"(r1), "=r"(r2), "=r"(r3) : "r"(addr))

__device__ __forceinline__ void mma_f16(float4& d, const uint32_t* a, uint32_t b0, uint32_t b1) {
    asm volatile("mma.sync.aligned.m16n8k16.row.col.f32.f16.f16.f32 "
                 "{%0,%1,%2,%3}, {%4,%5,%6,%7}, {%8,%9}, {%0,%1,%2,%3};"
                 : "+f"(d.x), "+f"(d.y), "+f"(d.z), "+f"(d.w)
                 : "r"(a[0]), "r"(a[1]), "r"(a[2]), "r"(a[3]), "r"(b0), "r"(b1));
}

__device__ __forceinline__ void cp16(uint32_t s, const void* g) {
    asm volatile("cp.async.cg.shared.global [%0], [%1], 16;" :: "r"(s), "l"(g));
}
__device__ __forceinline__ void cp_commit() {
    asm volatile("cp.async.commit_group;" ::: "memory");
}
template <int N>
__device__ __forceinline__ void cp_wait() {
    asm volatile("cp.async.wait_group %0;" :: "n"(N) : "memory");
}

__device__ __forceinline__ unsigned pack_h2(float a, float b) {
    __half2 h = __floats2half2_rn(a, b);
    return *(unsigned*)&h;
}

// ============================================================================
// fused split: z<4 -> weights fp16, z==4 -> x fp16
// ============================================================================
__global__ __launch_bounds__(256)
void split5_kernel(const float4* __restrict__ w0, const float4* __restrict__ w1,
                   const float4* __restrict__ w2, const float4* __restrict__ w3,
                   const float4* __restrict__ x)
{
    const int z = blockIdx.z;
    const float4* src;
    uint2* dst;
    int n4;
    if (z < 4) {
        src = (z == 0) ? w0 : (z == 1) ? w1 : (z == 2) ? w2 : w3;
        dst = (uint2*)(g_w16 + (size_t)z * DM * DM);
        n4 = DM * DM / 4;
    } else {
        src = x;
        dst = (uint2*)g_x16;
        n4 = SQ * DM / 4;
    }
    for (int i = blockIdx.x * blockDim.x + threadIdx.x; i < n4;
         i += gridDim.x * blockDim.x) {
        float4 v = src[i];
        dst[i] = make_uint2(pack_h2(v.x, v.y), pack_h2(v.z, v.w));
    }
}

// ============================================================================
// GEMM via mma.sync: 128x128 CTA tile, 4 warps (2x2), 64x64 per warp.
// K-chunk 32, ring-4 cp.async (wait<2>), XOR swizzle, ONE sync per chunk.
// 128 threads, launch_bounds(128,2) -> 256-reg cap, 2 CTAs/SM.
// ============================================================================
#define G_STG 16384
#define GA 0
#define GB 8192

__device__ __forceinline__ uint32_t gswz(int row, int ch) {
    return (uint32_t)(row * 64 + ((ch ^ ((row >> 1) & 3)) << 4));
}

template <int MODE>
__global__ __launch_bounds__(128, 2)
void gemm_mma(const __half* __restrict__ A,
              int wslot,
              const float* __restrict__ b0p, const float* __restrict__ b1p,
              const float* __restrict__ b2p,
              float* __restrict__ out)
{
    extern __shared__ __align__(16) char smem[];
    const uint32_t sb = smem_u32(smem);

    const int t = threadIdx.x;
    const int warp = t >> 5, lane = t & 31;
    const int warpM = warp >> 1, warpN = warp & 1;
    const int z = blockIdx.z;
    const int blockM = blockIdx.y * 128;
    const int blockN = blockIdx.x * 128;

    const __half* W = g_w16 + (size_t)(wslot + z) * DM * DM;
    const float* bias = (z == 0) ? b0p : ((z == 1) ? b1p : b2p);

    // loader: thread t handles row t of BOTH A and B (4 cp16 each)
    const __half* lsrcA = A + (size_t)(blockM + t) * DM;
    const __half* lsrcB = W + (size_t)(blockN + t) * DM;

    float4 acc[4][8];
#pragma unroll
    for (int i = 0; i < 4; i++)
#pragma unroll
        for (int j = 0; j < 8; j++) acc[i][j] = make_float4(0.f, 0.f, 0.f, 0.f);

    // prologue: chunks 0,1,2 -> stages 0,1,2
#pragma unroll
    for (int pc = 0; pc < 3; pc++) {
        const uint32_t stg = sb + pc * G_STG;
        const int kc = pc * 32;
#pragma unroll
        for (int ch = 0; ch < 4; ch++) {
            cp16(stg + GA + gswz(t, ch), lsrcA + kc + ch * 8);
            cp16(stg + GB + gswz(t, ch), lsrcB + kc + ch * 8);
        }
        cp_commit();
    }

    for (int c = 0; c < 32; c++) {
        cp_wait<2>();
        __syncthreads();

        const uint32_t stg = sb + (c & 3) * G_STG;
#pragma unroll
        for (int ks = 0; ks < 2; ks++) {
            const int chA = 2 * ks + (lane >> 4);
            const int chB = 2 * ks + ((lane >> 3) & 1);

            uint32_t a[4][4];
#pragma unroll
            for (int i = 0; i < 4; i++) {
                const int arow = warpM * 64 + i * 16 + (lane & 15);
                LDSM_X4(a[i][0], a[i][1], a[i][2], a[i][3],
                        stg + GA + gswz(arow, chA));
            }
            uint32_t bw[8][2];
#pragma unroll
            for (int p = 0; p < 4; p++) {
                const int brow = warpN * 64 + p * 16 + ((lane >> 4) * 8) + (lane & 7);
                uint32_t m0, m1, m2, m3;
                LDSM_X4(m0, m1, m2, m3, stg + GB + gswz(brow, chB));
                bw[2 * p][0] = m0; bw[2 * p][1] = m1;
                bw[2 * p + 1][0] = m2; bw[2 * p + 1][1] = m3;
            }
#pragma unroll
            for (int i = 0; i < 4; i++)
#pragma unroll
                for (int j = 0; j < 8; j++)
                    mma_f16(acc[i][j], a[i], bw[j][0], bw[j][1]);
        }

        // refill stage (c+3)&3 with chunk c+3 (last read at c-1; top sync fences)
        if (c + 3 < 32) {
            const uint32_t stg2 = sb + ((c + 3) & 3) * G_STG;
            const int kc = (c + 3) * 32;
#pragma unroll
            for (int ch = 0; ch < 4; ch++) {
                cp16(stg2 + GA + gswz(t, ch), lsrcA + kc + ch * 8);
                cp16(stg2 + GB + gswz(t, ch), lsrcB + kc + ch * 8);
            }
        }
        cp_commit();
    }

    // epilogue
    const float sc = (MODE == 0 && z == 0) ? (QSCALE * LOG2E) : 1.f;
#pragma unroll
    for (int i = 0; i < 4; i++) {
#pragma unroll
        for (int j = 0; j < 8; j++) {
            const int row0 = blockM + warpM * 64 + i * 16 + (lane >> 2);
            const int row1 = row0 + 8;
            const int col = blockN + warpN * 64 + j * 8 + (lane & 3) * 2;
            const float bx = bias[col], by = bias[col + 1];
            const float vx = (acc[i][j].x + bx) * sc;
            const float vy = (acc[i][j].y + by) * sc;
            const float vz = (acc[i][j].z + bx) * sc;
            const float vw = (acc[i][j].w + by) * sc;
            if (MODE == 1) {
                *(float2*)(out + (size_t)row0 * DM + col) = make_float2(vx, vy);
                *(float2*)(out + (size_t)row1 * DM + col) = make_float2(vz, vw);
            } else {
                const int hh = col >> 6, d = col & 63;
                const size_t a0 = (size_t)hh * SQ * HS + (size_t)row0 * HS + d;
                const size_t a1 = (size_t)hh * SQ * HS + (size_t)row1 * HS + d;
                __half* dst = (z == 0) ? g_q16 : ((z == 1) ? g_k16 : g_v16);
                *(uint32_t*)(dst + a0) = pack_h2(vx, vy);
                *(uint32_t*)(dst + a1) = pack_h2(vz, vw);
            }
        }
    }
}

// ============================================================================
// Flash attention: 4 warps x 32 q-rows (K/V fragments reused across 2 row
// blocks -> half the LDS traffic). Ring-4 cp.async, ONE sync/tile, exp2f.
// 128 threads, launch_bounds(128,2).
// ============================================================================
#define GSTB 144
#define KVBUF 18432
#define OFF_K 0
#define OFF_V 9216
#define ATTN_SMEM_TOT (4 * KVBUF)   // 73728

__global__ __launch_bounds__(128, 2)
void attn_mma()
{
    extern __shared__ __align__(16) char smem[];
    const uint32_t sb = smem_u32(smem);

    const int h  = blockIdx.y;
    const int qb = gridDim.x - 1 - blockIdx.x;
    const int t = threadIdx.x;
    const int warp = t >> 5, lane = t & 31;

    const size_t hbase = (size_t)h * SQ * HS;

    // ---- stage Q tile (128 rows x 128B): thread t copies row t ----
    {
        const size_t g = hbase + (size_t)(qb * 128 + t) * HS;
#pragma unroll
        for (int v = 0; v < 8; v++)
            *(uint4*)(smem + t * GSTB + v * 16) = *(const uint4*)(g_q16 + g + v * 8);
    }
    __syncthreads();

    // ---- Q fragments: warp owns rows warp*32 .. warp*32+31 (2 blocks) ----
    uint32_t qh[2][4][4];
#pragma unroll
    for (int i = 0; i < 2; i++)
#pragma unroll
        for (int ks = 0; ks < 4; ks++) {
            const uint32_t ro = (warp * 32 + i * 16 + (lane & 15)) * GSTB
                              + (ks * 16 + (lane >> 4) * 8) * 2;
            LDSM_X4(qh[i][ks][0], qh[i][ks][1], qh[i][ks][2], qh[i][ks][3], sb + ro);
        }
    __syncthreads();   // Q consumed before ring reuse

    const int nkt = 2 * qb + 2;

    // prologue: tiles 0..2 -> buffers 0..2 (guarded; 3 commits)
    // loader (128 threads): thread t -> row t>>1, 64B half (t&1)
#pragma unroll
    for (int i = 0; i < 3; i++) {
        if (i < nkt) {
            const uint32_t bufb = sb + i * KVBUF;
            const int r = t >> 1;
            const int c16 = (t & 1) * 32;       // fp16 offset: 0 or 32
            const size_t g = hbase + (size_t)(i * 64 + r) * HS + c16;
            const uint32_t so = r * GSTB + c16 * 2;
#pragma unroll
            for (int v = 0; v < 4; v++) {
                cp16(bufb + OFF_K + so + v * 16, g_k16 + g + v * 8);
                cp16(bufb + OFF_V + so + v * 16, g_v16 + g + v * 8);
            }
        }
        cp_commit();
    }

    float4 o[2][8];
#pragma unroll
    for (int i = 0; i < 2; i++)
#pragma unroll
        for (int f = 0; f < 8; f++) o[i][f] = make_float4(0.f, 0.f, 0.f, 0.f);
    float m_[2][2], l_[2][2];
#pragma unroll
    for (int i = 0; i < 2; i++) { m_[i][0] = m_[i][1] = -1e30f; l_[i][0] = l_[i][1] = 0.f; }

    for (int kt = 0; kt < nkt; kt++) {
        cp_wait<2>();
        __syncthreads();

        const uint32_t kvb = sb + (kt & 3) * KVBUF;

        // ---- S = Q K^T : K frags loaded once, used for both row blocks ----
        float4 s[2][8];
#pragma unroll
        for (int i = 0; i < 2; i++)
#pragma unroll
            for (int f = 0; f < 8; f++) s[i][f] = make_float4(0.f, 0.f, 0.f, 0.f);

#pragma unroll
        for (int ks = 0; ks < 4; ks++) {
            const uint32_t bcol = (ks * 16 + ((lane >> 3) & 1) * 8) * 2;
#pragma unroll
            for (int p = 0; p < 4; p++) {
                const uint32_t brow = (p * 16 + ((lane >> 4) * 8) + (lane & 7)) * GSTB;
                uint32_t k0, k1, k2, k3;
                LDSM_X4(k0, k1, k2, k3, kvb + OFF_K + brow + bcol);
#pragma unroll
                for (int i = 0; i < 2; i++) {
                    mma_f16(s[i][2 * p],     qh[i][ks], k0, k1);
                    mma_f16(s[i][2 * p + 1], qh[i][ks], k2, k3);
                }
            }
        }

        // ---- causal mask ----
        if (kt * 64 + 63 > qb * 128 + warp * 32) {
#pragma unroll
            for (int i = 0; i < 2; i++) {
                const int q0 = qb * 128 + warp * 32 + i * 16 + (lane >> 2);
                const int q1 = q0 + 8;
#pragma unroll
                for (int f = 0; f < 8; f++) {
                    const int kc = kt * 64 + f * 8 + (lane & 3) * 2;
                    if (kc > q0)     s[i][f].x = NEG;
                    if (kc + 1 > q0) s[i][f].y = NEG;
                    if (kc > q1)     s[i][f].z = NEG;
                    if (kc + 1 > q1) s[i][f].w = NEG;
                }
            }
        }

        // ---- online softmax (exp2 domain) per row block ----
#pragma unroll
        for (int i = 0; i < 2; i++) {
            float rmax0 = NEG, rmax1 = NEG;
#pragma unroll
            for (int f = 0; f < 8; f++) {
                rmax0 = fmaxf(rmax0, fmaxf(s[i][f].x, s[i][f].y));
                rmax1 = fmaxf(rmax1, fmaxf(s[i][f].z, s[i][f].w));
            }
            rmax0 = fmaxf(rmax0, __shfl_xor_sync(0xffffffffu, rmax0, 1));
            rmax0 = fmaxf(rmax0, __shfl_xor_sync(0xffffffffu, rmax0, 2));
            rmax1 = fmaxf(rmax1, __shfl_xor_sync(0xffffffffu, rmax1, 1));
            rmax1 = fmaxf(rmax1, __shfl_xor_sync(0xffffffffu, rmax1, 2));

            const float mn0 = fmaxf(m_[i][0], rmax0);
            const float mn1 = fmaxf(m_[i][1], rmax1);
            const float c0 = exp2f(m_[i][0] - mn0);
            const float c1 = exp2f(m_[i][1] - mn1);

            float rs0 = 0.f, rs1 = 0.f;
#pragma unroll
            for (int f = 0; f < 8; f++) {
                s[i][f].x = exp2f(s[i][f].x - mn0);
                s[i][f].y = exp2f(s[i][f].y - mn0);
                s[i][f].z = exp2f(s[i][f].z - mn1);
                s[i][f].w = exp2f(s[i][f].w - mn1);
                rs0 += s[i][f].x + s[i][f].y;
                rs1 += s[i][f].z + s[i][f].w;
            }
            rs0 += __shfl_xor_sync(0xffffffffu, rs0, 1);
            rs0 += __shfl_xor_sync(0xffffffffu, rs0, 2);
            rs1 += __shfl_xor_sync(0xffffffffu, rs1, 1);
            rs1 += __shfl_xor_sync(0xffffffffu, rs1, 2);

            l_[i][0] = l_[i][0] * c0 + rs0;
            l_[i][1] = l_[i][1] * c1 + rs1;
            m_[i][0] = mn0; m_[i][1] = mn1;
#pragma unroll
            for (int f = 0; f < 8; f++) {
                o[i][f].x *= c0; o[i][f].y *= c0; o[i][f].z *= c1; o[i][f].w *= c1;
            }
        }

        // ---- O += P V : V frags loaded once, used for both row blocks ----
#pragma unroll
        for (int ks = 0; ks < 4; ks++) {
            uint32_t ap[2][4];
#pragma unroll
            for (int i = 0; i < 2; i++) {
                ap[i][0] = pack_h2(s[i][2 * ks].x,     s[i][2 * ks].y);
                ap[i][1] = pack_h2(s[i][2 * ks].z,     s[i][2 * ks].w);
                ap[i][2] = pack_h2(s[i][2 * ks + 1].x, s[i][2 * ks + 1].y);
                ap[i][3] = pack_h2(s[i][2 * ks + 1].z, s[i][2 * ks + 1].w);
            }
            const uint32_t vrow = (ks * 16 + (lane & 7) + ((lane >> 3) & 1) * 8) * GSTB;
#pragma unroll
            for (int g = 0; g < 4; g++) {
                const uint32_t vcol = (g * 16 + (lane >> 4) * 8) * 2;
                uint32_t v0, v1, v2, v3;
                LDSM_X4_T(v0, v1, v2, v3, kvb + OFF_V + vrow + vcol);
#pragma unroll
                for (int i = 0; i < 2; i++) {
                    mma_f16(o[i][2 * g],     ap[i], v0, v1);
                    mma_f16(o[i][2 * g + 1], ap[i], v2, v3);
                }
            }
        }

        // ---- refill buffer (kt+3)&3 with tile kt+3 ----
        if (kt + 3 < nkt) {
            const uint32_t bufb = sb + ((kt + 3) & 3) * KVBUF;
            const int r = t >> 1;
            const int c16 = (t & 1) * 32;
            const size_t g = hbase + (size_t)((kt + 3) * 64 + r) * HS + c16;
            const uint32_t so = r * GSTB + c16 * 2;
#pragma unroll
            for (int v = 0; v < 4; v++) {
                cp16(bufb + OFF_K + so + v * 16, g_k16 + g + v * 8);
                cp16(bufb + OFF_V + so + v * 16, g_v16 + g + v * 8);
            }
        }
        cp_commit();
    }

    // ---- normalize + write fp16 (feeds O projection) ----
#pragma unroll
    for (int i = 0; i < 2; i++) {
        const float inv0 = 1.f / l_[i][0];
        const float inv1 = 1.f / l_[i][1];
        const int r0 = qb * 128 + warp * 32 + i * 16 + (lane >> 2);
        const int r1 = r0 + 8;
#pragma unroll
        for (int f = 0; f < 8; f++) {
            const int col = h * HS + f * 8 + (lane & 3) * 2;
            *(uint32_t*)(g_x16 + (size_t)r0 * DM + col) = pack_h2(o[i][f].x * inv0, o[i][f].y * inv0);
            *(uint32_t*)(g_x16 + (size_t)r1 * DM + col) = pack_h2(o[i][f].z * inv1, o[i][f].w * inv1);
        }
    }
}

// ============================================================================
// launch
// ============================================================================
extern "C" void kernel_launch(void* const* d_in, const int* in_sizes, int n_in,
                              void* d_out, int out_size)
{
    (void)in_sizes; (void)n_in; (void)out_size;
    const float* x  = (const float*)d_in[0];
    const float* wq = (const float*)d_in[1];
    const float* bq = (const float*)d_in[2];
    const float* wk = (const float*)d_in[3];
    const float* bk = (const float*)d_in[4];
    const float* wv = (const float*)d_in[5];
    const float* bv = (const float*)d_in[6];
    const float* wo = (const float*)d_in[7];
    const float* bo = (const float*)d_in[8];
    float* out = (float*)d_out;

    __half* x16;
    cudaGetSymbolAddress((void**)&x16, g_x16);

    const int GEMM_SMEM = 4 * G_STG;   // 65536
    cudaFuncSetAttribute(gemm_mma<0>,
                         cudaFuncAttributeMaxDynamicSharedMemorySize, GEMM_SMEM);
    cudaFuncSetAttribute(gemm_mma<1>,
                         cudaFuncAttributeMaxDynamicSharedMemorySize, GEMM_SMEM);
    cudaFuncSetAttribute(attn_mma,
                         cudaFuncAttributeMaxDynamicSharedMemorySize, ATTN_SMEM_TOT);

    split5_kernel<<<dim3(512, 1, 5), 256>>>((const float4*)wq, (const float4*)wk,
                                            (const float4*)wv, (const float4*)wo,
                                            (const float4*)x);

    gemm_mma<0><<<dim3(DM / 128, SQ / 128, 3), 128, GEMM_SMEM>>>(
        x16, 0, bq, bk, bv, nullptr);

    attn_mma<<<dim3(SQ / 128, NH), 128, ATTN_SMEM_TOT>>>();

    gemm_mma<1><<<dim3(DM / 128, SQ / 128, 1), 128, GEMM_SMEM>>>(
        x16, 3, bo, bo, bo, out);
}